// round 12
// baseline (speedup 1.0000x reference)
#include <cuda_runtime.h>
#include <cuda_bf16.h>
#include <cstdint>

// ---------------------------------------------------------------------------
// Convolution_29738353557732 : e3nn-style graph conv
// R12: crossbar-optimized k_edge (192 thr, 8 e/warp phase2, j-fixed phase1)
// ---------------------------------------------------------------------------

#define NMAX 50176
typedef unsigned long long ull;

__device__ float g_f  [NMAX * 160];
__device__ float g_sc [NMAX * 160];
__device__ float g_mid[NMAX * 384];

__device__ __forceinline__ void red4(float* p, float a, float b, float c, float d) {
    asm volatile("red.global.add.v4.f32 [%0], {%1,%2,%3,%4};"
                 :: "l"(p), "f"(a), "f"(b), "f"(c), "f"(d) : "memory");
}
__device__ __forceinline__ ull fdup(float x) {
    ull r; asm("mov.b64 %0, {%1, %1};" : "=l"(r) : "f"(x)); return r;
}
__device__ __forceinline__ void ffma2(ull& acc, ull a, ull b) {
    asm("fma.rn.f32x2 %0, %1, %2, %0;" : "+l"(acc) : "l"(a), "l"(b));
}
__device__ __forceinline__ float2 funpack(ull p) {
    float lo, hi; asm("mov.b64 {%0, %1}, %2;" : "=f"(lo), "=f"(hi) : "l"(p));
    return make_float2(lo, hi);
}

// ---------------------------------------------------------------- node pre
// 2 nodes per warp (R10, proven). Also zeroes g_mid.
#define PRE_SCW0 0
#define PRE_L1W0 16384
#define PRE_SCW1 32768
#define PRE_L1W1 36864
#define PRE_X    40960
#define PRE_SMEM 51200

__global__ __launch_bounds__(256) void k_nodepre(
    const float* __restrict__ x, const float* __restrict__ attr,
    const float* __restrict__ sc_w0, const float* __restrict__ sc_w1,
    const float* __restrict__ l1w0, const float* __restrict__ l1w1, int N)
{
    extern __shared__ unsigned char sbp[];
    float* s_scw0 = (float*)(sbp + PRE_SCW0);
    float* s_l1w0 = (float*)(sbp + PRE_L1W0);
    float* s_scw1 = (float*)(sbp + PRE_SCW1);
    float* s_l1w1 = (float*)(sbp + PRE_L1W1);
    float* s_x    = (float*)(sbp + PRE_X);     // 16 rows x 160

    {   // zero g_mid (grid-stride)
        float4* m4 = reinterpret_cast<float4*>(g_mid);
        int tot = N * 96;
        int stride = gridDim.x * 256;
        for (int i = blockIdx.x * 256 + threadIdx.x; i < tot; i += stride)
            m4[i] = make_float4(0.f, 0.f, 0.f, 0.f);
    }

    for (int i = threadIdx.x; i < 4096; i += 256) { s_scw0[i] = sc_w0[i]; s_l1w0[i] = l1w0[i]; }
    for (int i = threadIdx.x; i < 1024; i += 256) { s_scw1[i] = sc_w1[i]; s_l1w1[i] = l1w1[i]; }

    int wrp = threadIdx.x >> 5, l = threadIdx.x & 31;
    int n0 = blockIdx.x * 16 + wrp * 2;
    int n1 = n0 + 1;
    bool v0 = n0 < N, v1 = n1 < N;
    float* xr0 = &s_x[(wrp * 2) * 160];
    float* xr1 = &s_x[(wrp * 2 + 1) * 160];
    if (v0) {
#pragma unroll
        for (int i = 0; i < 5; i++) xr0[l + 32 * i] = x[(size_t)n0 * 160 + l + 32 * i];
    }
    if (v1) {
#pragma unroll
        for (int i = 0; i < 5; i++) xr1[l + 32 * i] = x[(size_t)n1 * 160 + l + 32 * i];
    }
    __syncthreads();
    if (!v0) return;

    float a0 = attr[n0];
    float a1 = v1 ? attr[n1] : 0.f;
    int w_[3], d_[3];
#pragma unroll
    for (int i = 0; i < 3; i++) { int o = l + 32 * i; w_[i] = o / 3; d_[i] = o - 3 * w_[i]; }

    ull af0 = 0ull, as0 = 0ull, af1 = 0ull, as1 = 0ull;
#pragma unroll 8
    for (int u = 0; u < 64; u++) {
        ull wl = *(const ull*)&s_l1w0[u * 64 + 2 * l];
        ull ws = *(const ull*)&s_scw0[u * 64 + 2 * l];
        ull x0 = fdup(xr0[u]);
        ull x1 = fdup(xr1[u]);
        ffma2(af0, x0, wl); ffma2(as0, x0, ws);
        ffma2(af1, x1, wl); ffma2(as1, x1, ws);
    }
    float fv0[3] = {0,0,0}, sv0[3] = {0,0,0}, fv1[3] = {0,0,0}, sv1[3] = {0,0,0};
#pragma unroll 4
    for (int u = 0; u < 32; u++) {
#pragma unroll
        for (int i = 0; i < 3; i++) {
            float wl = s_l1w1[u * 32 + w_[i]];
            float ws = s_scw1[u * 32 + w_[i]];
            float xv0 = xr0[64 + 3 * u + d_[i]];
            float xv1 = xr1[64 + 3 * u + d_[i]];
            fv0[i] += xv0 * wl;  sv0[i] += xv0 * ws;
            fv1[i] += xv1 * wl;  sv1[i] += xv1 * ws;
        }
    }
    {
        float* fo = &g_f[(size_t)n0 * 160];
        float* so = &g_sc[(size_t)n0 * 160];
        float S1 = 0.125f * a0, S2 = 0.17677669529663687f * a0;
        float2 ff = funpack(af0), ss = funpack(as0);
        *(float2*)&fo[2 * l] = make_float2(ff.x * S1, ff.y * S1);
        *(float2*)&so[2 * l] = make_float2(ss.x * S1, ss.y * S1);
#pragma unroll
        for (int i = 0; i < 3; i++) {
            fo[64 + l + 32 * i] = fv0[i] * S2;
            so[64 + l + 32 * i] = sv0[i] * S2;
        }
    }
    if (v1) {
        float* fo = &g_f[(size_t)n1 * 160];
        float* so = &g_sc[(size_t)n1 * 160];
        float S1 = 0.125f * a1, S2 = 0.17677669529663687f * a1;
        float2 ff = funpack(af1), ss = funpack(as1);
        *(float2*)&fo[2 * l] = make_float2(ff.x * S1, ff.y * S1);
        *(float2*)&so[2 * l] = make_float2(ss.x * S1, ss.y * S1);
#pragma unroll
        for (int i = 0; i < 3; i++) {
            fo[64 + l + 32 * i] = fv1[i] * S2;
            so[64 + l + 32 * i] = sv1[i] * S2;
        }
    }
}

// ---------------------------------------------------------------- edge kernel
// TILE_E=48, 192 threads (6 warps), 2 CTAs/SM.
// phase1: j fixed per thread (w1t hoisted), es broadcast float4, h -> s_h[j*52+e]
// phase2: warp = 8 edges x 192 outs; h via 2 broadcast LDS.128 + dups;
//         w as k-pairs (3 LDS.64); acc[8][3] f32x2.
// phase3: 8 edges/warp, prefetched gather + red.v4.
#define TILE_E 48
#define HS 52

#define O_H    0                    // 64*52*4      = 13312
#define O_W2   13312                // 49152
#define O_WT   62464                // 48*192*4     = 36864
#define O_W1T  99328                // 2048
#define O_ES   101376               // 48*8*4       = 1536
#define O_EA   102912               // 48*16       = 768
#define O_SRC  103680               // 192
#define O_DST  103872               // 192
#define O_G    104064               // 6*160*4      = 3840
#define K12_SMEM 107904

__global__ __launch_bounds__(192, 2) void k_edge(
    const float* __restrict__ edge_attr, const float* __restrict__ edge_scalars,
    const float* __restrict__ fc_w1, const float* __restrict__ fc_w2,
    const int* __restrict__ edge_src, const int* __restrict__ edge_dst, int E)
{
    extern __shared__ unsigned char sb[];
    float*  s_h   = (float*)(sb + O_H);
    float*  s_w2  = (float*)(sb + O_W2);
    float*  s_wt  = (float*)(sb + O_WT);
    float*  s_w1t = (float*)(sb + O_W1T);
    float*  s_es  = (float*)(sb + O_ES);     // stride 8
    float4* s_ea4 = (float4*)(sb + O_EA);
    int*    s_src = (int*)(sb + O_SRC);
    int*    s_dst = (int*)(sb + O_DST);
    float*  s_g   = (float*)(sb + O_G);

    const int tid = threadIdx.x;
    const int wrp = tid >> 5, l = tid & 31;

    for (int i = tid; i < 512; i += 192) {
        int c = i >> 6, j = i & 63;            // w1t[j*8+c] = fc_w1[c*64+j]
        s_w1t[j * 8 + c] = fc_w1[i];
    }
    for (int i = tid; i < 12288; i += 192) s_w2[i] = fc_w2[i] * 0.125f;
    __syncthreads();

    const int ntiles = (E + TILE_E - 1) / TILE_E;
    const int eb = wrp * 8;                    // phase-2/3: 8 edges per warp

    // phase-1 fixed assignment: j = tid & 63, e-group = tid >> 6 (0..2)
    const int p1j = tid & 63;
    const int p1eg = tid >> 6;
    const float4 wa = *(const float4*)&s_w1t[p1j * 8];
    const float4 wb = *(const float4*)&s_w1t[p1j * 8 + 4];

    for (int tile = blockIdx.x; tile < ntiles; tile += gridDim.x) {
        const int e0 = tile * TILE_E;

        // ---- stage per-edge inputs
        if (tid < 96) {                         // es: 2 float4 per edge, stride 8
            int e = tid >> 1, h = tid & 1, ge = e0 + e;
            float4 v = make_float4(0.f, 0.f, 0.f, 0.f);
            if (ge < E) v = *(const float4*)&edge_scalars[(size_t)ge * 8 + 4 * h];
            *(float4*)&s_es[e * 8 + 4 * h] = v;
        } else if (tid < 144) {                 // ea
            int e = tid - 96, ge = e0 + e;
            s_ea4[e] = (ge < E) ? *(const float4*)&edge_attr[(size_t)ge * 4]
                                : make_float4(0.f, 0.f, 0.f, 0.f);
        } else {                                // src + dst
            int e = tid - 144, ge = e0 + e;
            s_src[e] = (ge < E) ? edge_src[ge] : 0;
            s_dst[e] = (ge < E) ? edge_dst[ge] : 0;
        }
        __syncthreads();

        // ---- phase 1: h = silu(es @ fc_w1 / sqrt(8)); j fixed, e = eg + 3k
#pragma unroll
        for (int k = 0; k < 16; k++) {
            int e = p1eg + 3 * k;
            float4 ea_ = *(const float4*)&s_es[e * 8];
            float4 eb_ = *(const float4*)&s_es[e * 8 + 4];
            float acc = ea_.x * wa.x + ea_.y * wa.y + ea_.z * wa.z + ea_.w * wa.w
                      + eb_.x * wb.x + eb_.y * wb.y + eb_.z * wb.z + eb_.w * wb.w;
            acc *= 0.3535533905932738f;
            s_h[p1j * HS + e] = __fdividef(acc, 1.f + __expf(-acc));
        }
        __syncthreads();

        // ---- phase 2: wt = h @ (0.125*w2); warp = 8 edges x 192 outs
        {
            ull acc[8][3];
#pragma unroll
            for (int a = 0; a < 8; a++)
#pragma unroll
                for (int b = 0; b < 3; b++) acc[a][b] = 0ull;

#pragma unroll 4
            for (int j = 0; j < 64; j++) {
                const float4* hp = (const float4*)&s_h[j * HS + eb];
                float4 ha = hp[0], hb = hp[1];
                ull hd[8];
                hd[0] = fdup(ha.x); hd[1] = fdup(ha.y);
                hd[2] = fdup(ha.z); hd[3] = fdup(ha.w);
                hd[4] = fdup(hb.x); hd[5] = fdup(hb.y);
                hd[6] = fdup(hb.z); hd[7] = fdup(hb.w);
                const ull* wp = (const ull*)&s_w2[j * 192 + 2 * l];
                ull w0 = wp[0], w1v = wp[32], w2v = wp[64];
#pragma unroll
                for (int e = 0; e < 8; e++) {
                    ffma2(acc[e][0], hd[e], w0);
                    ffma2(acc[e][1], hd[e], w1v);
                    ffma2(acc[e][2], hd[e], w2v);
                }
            }
#pragma unroll
            for (int e = 0; e < 8; e++) {
                ull* outp = (ull*)&s_wt[(eb + e) * 192 + 2 * l];
                outp[0]  = acc[e][0];
                outp[32] = acc[e][1];
                outp[64] = acc[e][2];
            }
        }
        __syncthreads();

        // ---- phase 3: prefetched gather + features + red.v4 scatter
        {
            float* gw = &s_g[wrp * 160];
            float4* gw4 = (float4*)gw;

            float4 pa, pb;
            {
                const float4* fr = (const float4*)&g_f[(size_t)s_src[eb] * 160];
                pa = fr[l];
                pb = (l < 8) ? fr[32 + l] : make_float4(0.f, 0.f, 0.f, 0.f);
            }

#pragma unroll
            for (int ee = 0; ee < 8; ee++) {
                const int e = eb + ee;
                const bool valid = (e0 + e) < E;

                gw4[l] = pa;
                if (l < 8) gw4[32 + l] = pb;
                if (ee < 7) {
                    const float4* fr = (const float4*)&g_f[(size_t)s_src[e + 1] * 160];
                    pa = fr[l];
                    if (l < 8) pb = fr[32 + l];
                }
                __syncwarp();

                float4 ea = s_ea4[e];
                const float ys = ea.x, yv0 = ea.y, yv1 = ea.z, yv2 = ea.w;
                const float* wt = &s_wt[e * 192];
                float* mb = &g_mid[(size_t)s_dst[e] * 384];

#pragma unroll
                for (int i = 0; i < 3; i++) {
                    const int t0 = i * 128 + 4 * l;
                    float v[4];
                    if (t0 < 64) {                       // m0a
#pragma unroll
                        for (int j = 0; j < 4; j++) v[j] = gw[t0 + j] * ys * wt[t0 + j];
                    } else if (t0 < 96) {                // m0b
                        const int c0 = t0 - 64;
#pragma unroll
                        for (int j = 0; j < 4; j++) {
                            int c = c0 + j;
                            float dot = gw[64 + 3 * c] * yv0 + gw[65 + 3 * c] * yv1
                                      + gw[66 + 3 * c] * yv2;
                            v[j] = dot * 0.5773502691896258f * wt[160 + c];
                        }
                    } else if (t0 < 288) {               // m1a
                        const int s0 = t0 - 96;
#pragma unroll
                        for (int j = 0; j < 4; j++) {
                            int s = s0 + j;
                            int u = s / 3, d = s - 3 * u;
                            float yvd = (d == 0) ? yv0 : ((d == 1) ? yv1 : yv2);
                            v[j] = gw[u] * yvd * wt[64 + u];
                        }
                    } else {                             // m1b
                        const int s0 = t0 - 288;
#pragma unroll
                        for (int j = 0; j < 4; j++) {
                            int s = s0 + j;
                            int u = s / 3;
                            v[j] = gw[64 + s] * ys * wt[128 + u];
                        }
                    }
                    if (valid) red4(&mb[t0], v[0], v[1], v[2], v[3]);
                }
                __syncwarp();
            }
        }
        __syncthreads();
    }
}

// ---------------------------------------------------------------- node post
// 2 nodes per warp (R10, proven).
#define PST_W0  0
#define PST_W1  24576
#define PST_L3  36864
#define PST_MID 37376
#define PST_SMEM 61952

__global__ __launch_bounds__(256) void k_nodepost(
    const float* __restrict__ attr, const float* __restrict__ l2w0,
    const float* __restrict__ l2w1, const float* __restrict__ l3,
    const int* __restrict__ nn, float* __restrict__ out, int N)
{
    extern __shared__ unsigned char sbq[];
    float* s_w0  = (float*)(sbq + PST_W0);
    float* s_w1  = (float*)(sbq + PST_W1);
    float* s_l3  = (float*)(sbq + PST_L3);
    float* s_mid = (float*)(sbq + PST_MID);   // 16 rows x 384

    for (int i = threadIdx.x; i < 6144; i += 256) s_w0[i] = l2w0[i];
    for (int i = threadIdx.x; i < 3072; i += 256) s_w1[i] = l2w1[i];
    if (threadIdx.x < 96) s_l3[threadIdx.x] = l3[threadIdx.x];

    float ms = rsqrtf((float)nn[0]);
    const float SC = 0.10206207261596575f;
    int wrp = threadIdx.x >> 5, l = threadIdx.x & 31;
    int n0 = blockIdx.x * 16 + wrp * 2;
    int n1 = n0 + 1;
    bool v0 = n0 < N, v1 = n1 < N;
    float* mr0 = &s_mid[(wrp * 2) * 384];
    float* mr1 = &s_mid[(wrp * 2 + 1) * 384];
    if (v0) {
#pragma unroll
        for (int i = 0; i < 12; i++) mr0[l + 32 * i] = g_mid[(size_t)n0 * 384 + l + 32 * i];
    }
    if (v1) {
#pragma unroll
        for (int i = 0; i < 12; i++) mr1[l + 32 * i] = g_mid[(size_t)n1 * 384 + l + 32 * i];
    }
    __syncthreads();
    if (!v0) return;

    float a0 = attr[n0];
    float a1 = v1 ? attr[n1] : 0.f;
    int w_[3], d_[3];
#pragma unroll
    for (int i = 0; i < 3; i++) { int o = l + 32 * i; w_[i] = o / 3; d_[i] = o - 3 * w_[i]; }

    ull c0 = 0ull, c1 = 0ull;
    float ang0 = 0.f, ang1 = 0.f;
#pragma unroll 8
    for (int u = 0; u < 96; u++) {
        ull w = *(const ull*)&s_w0[u * 64 + 2 * l];
        float m0 = mr0[u], m1 = mr1[u];
        ffma2(c0, fdup(m0), w);
        ffma2(c1, fdup(m1), w);
        float lw = s_l3[u];
        ang0 += m0 * lw;
        ang1 += m1 * lw;
    }
    float cv0[3] = {0,0,0}, cv1[3] = {0,0,0};
#pragma unroll 4
    for (int u = 0; u < 96; u++) {
#pragma unroll
        for (int i = 0; i < 3; i++) {
            float w = s_w1[u * 32 + w_[i]];
            cv0[i] += mr0[96 + 3 * u + d_[i]] * w;
            cv1[i] += mr1[96 + 3 * u + d_[i]] * w;
        }
    }
    {
        float sA = SC * ms * a0;
        float angle = 0.1f * ang0 * sA;
        float sa, ca; sincosf(angle, &sa, &ca);
        const float* scrow = &g_sc[(size_t)n0 * 160];
        float* orow = &out[(size_t)n0 * 160];
        float2 cc = funpack(c0);
        float2 sc2 = *(const float2*)&scrow[2 * l];
        *(float2*)&orow[2 * l] = make_float2(ca * sc2.x + sa * (cc.x * sA),
                                             ca * sc2.y + sa * (cc.y * sA));
#pragma unroll
        for (int i = 0; i < 3; i++)
            orow[64 + l + 32 * i] = ca * scrow[64 + l + 32 * i] + sa * (cv0[i] * sA);
    }
    if (v1) {
        float sA = SC * ms * a1;
        float angle = 0.1f * ang1 * sA;
        float sa, ca; sincosf(angle, &sa, &ca);
        const float* scrow = &g_sc[(size_t)n1 * 160];
        float* orow = &out[(size_t)n1 * 160];
        float2 cc = funpack(c1);
        float2 sc2 = *(const float2*)&scrow[2 * l];
        *(float2*)&orow[2 * l] = make_float2(ca * sc2.x + sa * (cc.x * sA),
                                             ca * sc2.y + sa * (cc.y * sA));
#pragma unroll
        for (int i = 0; i < 3; i++)
            orow[64 + l + 32 * i] = ca * scrow[64 + l + 32 * i] + sa * (cv1[i] * sA);
    }
}

// ---------------------------------------------------------------- launch
extern "C" void kernel_launch(void* const* d_in, const int* in_sizes, int n_in,
                              void* d_out, int out_size)
{
    const float* node_input   = (const float*)d_in[0];
    const float* node_attr    = (const float*)d_in[1];
    const float* edge_attr    = (const float*)d_in[2];
    const float* edge_scalars = (const float*)d_in[3];
    const float* sc_w0        = (const float*)d_in[4];
    const float* sc_w1        = (const float*)d_in[5];
    const float* lin1_w0      = (const float*)d_in[6];
    const float* lin1_w1      = (const float*)d_in[7];
    const float* fc_w1        = (const float*)d_in[8];
    const float* fc_w2        = (const float*)d_in[9];
    const float* lin2_w0      = (const float*)d_in[10];
    const float* lin2_w1      = (const float*)d_in[11];
    const float* lin3_w       = (const float*)d_in[12];
    const int*   edge_src     = (const int*)d_in[13];
    const int*   edge_dst     = (const int*)d_in[14];
    const int*   num_neigh    = (const int*)d_in[15];
    float* out = (float*)d_out;

    int N = in_sizes[0] / 160;
    int E = in_sizes[2] / 4;

    cudaFuncSetAttribute(k_nodepre, cudaFuncAttributeMaxDynamicSharedMemorySize, PRE_SMEM);
    k_nodepre<<<(N + 15) / 16, 256, PRE_SMEM>>>(node_input, node_attr, sc_w0, sc_w1,
                                                lin1_w0, lin1_w1, N);

    cudaFuncSetAttribute(k_edge, cudaFuncAttributeMaxDynamicSharedMemorySize, K12_SMEM);
    k_edge<<<296, 192, K12_SMEM>>>(edge_attr, edge_scalars, fc_w1, fc_w2,
                                   edge_src, edge_dst, E);

    cudaFuncSetAttribute(k_nodepost, cudaFuncAttributeMaxDynamicSharedMemorySize, PST_SMEM);
    k_nodepost<<<(N + 15) / 16, 256, PST_SMEM>>>(node_attr, lin2_w0, lin2_w1, lin3_w,
                                                 num_neigh, out, N);
}

// round 15
// speedup vs baseline: 1.1643x; 1.1643x over previous
#include <cuda_runtime.h>
#include <cuda_bf16.h>
#include <cstdint>

// ---------------------------------------------------------------------------
// Convolution_29738353557732 : e3nn-style graph conv
// R13: R11 base; k_edge phase-1 reg-hoisted w1 + broadcast es (stride-50 s_h);
//      dummy launch inserted so ncu captures k_edge next round.
// ---------------------------------------------------------------------------

#define NMAX 50176
typedef unsigned long long ull;

__device__ float g_f  [NMAX * 160];
__device__ float g_sc [NMAX * 160];
__device__ float g_mid[NMAX * 384];

__device__ __forceinline__ void red4(float* p, float a, float b, float c, float d) {
    asm volatile("red.global.add.v4.f32 [%0], {%1,%2,%3,%4};"
                 :: "l"(p), "f"(a), "f"(b), "f"(c), "f"(d) : "memory");
}
__device__ __forceinline__ ull fdup(float x) {
    ull r; asm("mov.b64 %0, {%1, %1};" : "=l"(r) : "f"(x)); return r;
}
__device__ __forceinline__ void ffma2(ull& acc, ull a, ull b) {
    asm("fma.rn.f32x2 %0, %1, %2, %0;" : "+l"(acc) : "l"(a), "l"(b));
}
__device__ __forceinline__ float2 funpack(ull p) {
    float lo, hi; asm("mov.b64 {%0, %1}, %2;" : "=f"(lo), "=f"(hi) : "l"(p));
    return make_float2(lo, hi);
}

__global__ void k_dummy() {}

// ---------------------------------------------------------------- node pre
// 2 nodes per warp (proven). Also zeroes g_mid.
#define PRE_SCW0 0
#define PRE_L1W0 16384
#define PRE_SCW1 32768
#define PRE_L1W1 36864
#define PRE_X    40960
#define PRE_SMEM 51200

__global__ __launch_bounds__(256) void k_nodepre(
    const float* __restrict__ x, const float* __restrict__ attr,
    const float* __restrict__ sc_w0, const float* __restrict__ sc_w1,
    const float* __restrict__ l1w0, const float* __restrict__ l1w1, int N)
{
    extern __shared__ unsigned char sbp[];
    float* s_scw0 = (float*)(sbp + PRE_SCW0);
    float* s_l1w0 = (float*)(sbp + PRE_L1W0);
    float* s_scw1 = (float*)(sbp + PRE_SCW1);
    float* s_l1w1 = (float*)(sbp + PRE_L1W1);
    float* s_x    = (float*)(sbp + PRE_X);     // 16 rows x 160

    {   // zero g_mid (grid-stride)
        float4* m4 = reinterpret_cast<float4*>(g_mid);
        int tot = N * 96;
        int stride = gridDim.x * 256;
        for (int i = blockIdx.x * 256 + threadIdx.x; i < tot; i += stride)
            m4[i] = make_float4(0.f, 0.f, 0.f, 0.f);
    }

    for (int i = threadIdx.x; i < 4096; i += 256) { s_scw0[i] = sc_w0[i]; s_l1w0[i] = l1w0[i]; }
    for (int i = threadIdx.x; i < 1024; i += 256) { s_scw1[i] = sc_w1[i]; s_l1w1[i] = l1w1[i]; }

    int wrp = threadIdx.x >> 5, l = threadIdx.x & 31;
    int n0 = blockIdx.x * 16 + wrp * 2;
    int n1 = n0 + 1;
    bool v0 = n0 < N, v1 = n1 < N;
    float* xr0 = &s_x[(wrp * 2) * 160];
    float* xr1 = &s_x[(wrp * 2 + 1) * 160];
    if (v0) {
#pragma unroll
        for (int i = 0; i < 5; i++) xr0[l + 32 * i] = x[(size_t)n0 * 160 + l + 32 * i];
    }
    if (v1) {
#pragma unroll
        for (int i = 0; i < 5; i++) xr1[l + 32 * i] = x[(size_t)n1 * 160 + l + 32 * i];
    }
    __syncthreads();
    if (!v0) return;

    float a0 = attr[n0];
    float a1 = v1 ? attr[n1] : 0.f;
    int w_[3], d_[3];
#pragma unroll
    for (int i = 0; i < 3; i++) { int o = l + 32 * i; w_[i] = o / 3; d_[i] = o - 3 * w_[i]; }

    ull af0 = 0ull, as0 = 0ull, af1 = 0ull, as1 = 0ull;
#pragma unroll 8
    for (int u = 0; u < 64; u++) {
        ull wl = *(const ull*)&s_l1w0[u * 64 + 2 * l];
        ull ws = *(const ull*)&s_scw0[u * 64 + 2 * l];
        ull x0 = fdup(xr0[u]);
        ull x1 = fdup(xr1[u]);
        ffma2(af0, x0, wl); ffma2(as0, x0, ws);
        ffma2(af1, x1, wl); ffma2(as1, x1, ws);
    }
    float fv0[3] = {0,0,0}, sv0[3] = {0,0,0}, fv1[3] = {0,0,0}, sv1[3] = {0,0,0};
#pragma unroll 4
    for (int u = 0; u < 32; u++) {
#pragma unroll
        for (int i = 0; i < 3; i++) {
            float wl = s_l1w1[u * 32 + w_[i]];
            float ws = s_scw1[u * 32 + w_[i]];
            float xv0 = xr0[64 + 3 * u + d_[i]];
            float xv1 = xr1[64 + 3 * u + d_[i]];
            fv0[i] += xv0 * wl;  sv0[i] += xv0 * ws;
            fv1[i] += xv1 * wl;  sv1[i] += xv1 * ws;
        }
    }
    {
        float* fo = &g_f[(size_t)n0 * 160];
        float* so = &g_sc[(size_t)n0 * 160];
        float S1 = 0.125f * a0, S2 = 0.17677669529663687f * a0;
        float2 ff = funpack(af0), ss = funpack(as0);
        *(float2*)&fo[2 * l] = make_float2(ff.x * S1, ff.y * S1);
        *(float2*)&so[2 * l] = make_float2(ss.x * S1, ss.y * S1);
#pragma unroll
        for (int i = 0; i < 3; i++) {
            fo[64 + l + 32 * i] = fv0[i] * S2;
            so[64 + l + 32 * i] = sv0[i] * S2;
        }
    }
    if (v1) {
        float* fo = &g_f[(size_t)n1 * 160];
        float* so = &g_sc[(size_t)n1 * 160];
        float S1 = 0.125f * a1, S2 = 0.17677669529663687f * a1;
        float2 ff = funpack(af1), ss = funpack(as1);
        *(float2*)&fo[2 * l] = make_float2(ff.x * S1, ff.y * S1);
        *(float2*)&so[2 * l] = make_float2(ss.x * S1, ss.y * S1);
#pragma unroll
        for (int i = 0; i < 3; i++) {
            fo[64 + l + 32 * i] = fv1[i] * S2;
            so[64 + l + 32 * i] = sv1[i] * S2;
        }
    }
}

// ---------------------------------------------------------------- edge kernel
// TILE_E=48, 256 threads, 2 CTAs/SM (R11 structure).
// phase1: j fixed per thread (w1 in regs), es broadcast LDS.128, s_h stride 50.
// phase2: warp = 6 edges x 192 outs (k-pair f32x2).  phase3: 6 e/warp scatter.
#define TILE_E 48
#define HS 50

#define O_H    0                    // 64*50*4      = 12800
#define O_W2   12800                // 49152
#define O_WT   61952                // 48*192*4     = 36864
#define O_W1T  98816                // 2048
#define O_ES   100864               // 48*8*4       = 1536
#define O_EA   102400               // 768
#define O_SRC  103168               // 192
#define O_DST  103360               // 192
#define O_G    103552               // 8*160*4      = 5120
#define K13_SMEM 108672

__global__ __launch_bounds__(256, 2) void k_edge(
    const float* __restrict__ edge_attr, const float* __restrict__ edge_scalars,
    const float* __restrict__ fc_w1, const float* __restrict__ fc_w2,
    const int* __restrict__ edge_src, const int* __restrict__ edge_dst, int E)
{
    extern __shared__ unsigned char sb[];
    float*  s_h   = (float*)(sb + O_H);
    float*  s_w2  = (float*)(sb + O_W2);
    float*  s_wt  = (float*)(sb + O_WT);
    float*  s_w1t = (float*)(sb + O_W1T);
    float*  s_es  = (float*)(sb + O_ES);     // stride 8
    float4* s_ea4 = (float4*)(sb + O_EA);
    int*    s_src = (int*)(sb + O_SRC);
    int*    s_dst = (int*)(sb + O_DST);
    float*  s_g   = (float*)(sb + O_G);

    const int tid = threadIdx.x;
    const int wrp = tid >> 5, l = tid & 31;

    for (int i = tid; i < 512; i += 256) {
        int c = i >> 6, j = i & 63;            // w1t[j*8+c] = fc_w1[c*64+j]
        s_w1t[j * 8 + c] = fc_w1[i];
    }
    for (int i = tid; i < 12288; i += 256) s_w2[i] = fc_w2[i] * 0.125f;
    __syncthreads();

    const int ntiles = (E + TILE_E - 1) / TILE_E;
    const int eb = wrp * 6;                    // phase-2/3: 6 edges per warp

    // phase-1 fixed assignment: j = tid & 63, e-group = tid >> 6 (0..3)
    const int p1j = tid & 63;
    const int p1eg = tid >> 6;
    const float4 wa = *(const float4*)&s_w1t[p1j * 8];
    const float4 wb = *(const float4*)&s_w1t[p1j * 8 + 4];
    float* const p1out = &s_h[p1j * HS];

    for (int tile = blockIdx.x; tile < ntiles; tile += gridDim.x) {
        const int e0 = tile * TILE_E;

        // ---- stage per-edge inputs
        if (tid < 96) {                         // es: 2 float4 per edge, stride 8
            int e = tid >> 1, h = tid & 1, ge = e0 + e;
            float4 v = make_float4(0.f, 0.f, 0.f, 0.f);
            if (ge < E) v = *(const float4*)&edge_scalars[(size_t)ge * 8 + 4 * h];
            *(float4*)&s_es[e * 8 + 4 * h] = v;
        } else if (tid < 144) {                 // ea
            int e = tid - 96, ge = e0 + e;
            s_ea4[e] = (ge < E) ? *(const float4*)&edge_attr[(size_t)ge * 4]
                                : make_float4(0.f, 0.f, 0.f, 0.f);
        } else if (tid < 192) {                 // src + dst
            int e = tid - 144, ge = e0 + e;
            s_src[e] = (ge < E) ? edge_src[ge] : 0;
            s_dst[e] = (ge < E) ? edge_dst[ge] : 0;
        }
        __syncthreads();

        // ---- phase 1: h = silu(es @ fc_w1 / sqrt(8)); j fixed, e = eg + 4k
#pragma unroll
        for (int k = 0; k < 12; k++) {
            int e = p1eg + 4 * k;
            float4 A = *(const float4*)&s_es[e * 8];
            float4 B = *(const float4*)&s_es[e * 8 + 4];
            float acc = A.x * wa.x + A.y * wa.y + A.z * wa.z + A.w * wa.w
                      + B.x * wb.x + B.y * wb.y + B.z * wb.z + B.w * wb.w;
            acc *= 0.3535533905932738f;
            p1out[e] = __fdividef(acc, 1.f + __expf(-acc));
        }
        __syncthreads();

        // ---- phase 2: wt = h @ (0.125*w2); warp = 6 edges x 192 outs
        {
            ull acc[6][3];
#pragma unroll
            for (int a = 0; a < 6; a++)
#pragma unroll
                for (int b = 0; b < 3; b++) acc[a][b] = 0ull;

#pragma unroll 4
            for (int j = 0; j < 64; j++) {
                const float2* hp = (const float2*)&s_h[j * HS + eb];
                float2 h01 = hp[0], h23 = hp[1], h45 = hp[2];
                ull hd[6];
                hd[0] = fdup(h01.x); hd[1] = fdup(h01.y);
                hd[2] = fdup(h23.x); hd[3] = fdup(h23.y);
                hd[4] = fdup(h45.x); hd[5] = fdup(h45.y);
                const ull* wp = (const ull*)&s_w2[j * 192 + 2 * l];
                ull w0 = wp[0], w1v = wp[32], w2v = wp[64];
#pragma unroll
                for (int e = 0; e < 6; e++) {
                    ffma2(acc[e][0], hd[e], w0);
                    ffma2(acc[e][1], hd[e], w1v);
                    ffma2(acc[e][2], hd[e], w2v);
                }
            }
#pragma unroll
            for (int e = 0; e < 6; e++) {
                ull* outp = (ull*)&s_wt[(eb + e) * 192 + 2 * l];
                outp[0]  = acc[e][0];
                outp[32] = acc[e][1];
                outp[64] = acc[e][2];
            }
        }
        __syncthreads();

        // ---- phase 3: prefetched gather + features + red.v4 scatter
        {
            float* gw = &s_g[wrp * 160];
            float4* gw4 = (float4*)gw;

            float4 pa, pb;
            {
                const float4* fr = (const float4*)&g_f[(size_t)s_src[eb] * 160];
                pa = fr[l];
                pb = (l < 8) ? fr[32 + l] : make_float4(0.f, 0.f, 0.f, 0.f);
            }

#pragma unroll
            for (int ee = 0; ee < 6; ee++) {
                const int e = eb + ee;
                const bool valid = (e0 + e) < E;

                gw4[l] = pa;
                if (l < 8) gw4[32 + l] = pb;
                if (ee < 5) {
                    const float4* fr = (const float4*)&g_f[(size_t)s_src[e + 1] * 160];
                    pa = fr[l];
                    if (l < 8) pb = fr[32 + l];
                }
                __syncwarp();

                float4 ea = s_ea4[e];
                const float ys = ea.x, yv0 = ea.y, yv1 = ea.z, yv2 = ea.w;
                const float* wt = &s_wt[e * 192];
                float* mb = &g_mid[(size_t)s_dst[e] * 384];

#pragma unroll
                for (int i = 0; i < 3; i++) {
                    const int t0 = i * 128 + 4 * l;
                    float v[4];
                    if (t0 < 64) {                       // m0a
#pragma unroll
                        for (int j = 0; j < 4; j++) v[j] = gw[t0 + j] * ys * wt[t0 + j];
                    } else if (t0 < 96) {                // m0b
                        const int c0 = t0 - 64;
#pragma unroll
                        for (int j = 0; j < 4; j++) {
                            int c = c0 + j;
                            float dot = gw[64 + 3 * c] * yv0 + gw[65 + 3 * c] * yv1
                                      + gw[66 + 3 * c] * yv2;
                            v[j] = dot * 0.5773502691896258f * wt[160 + c];
                        }
                    } else if (t0 < 288) {               // m1a
                        const int s0 = t0 - 96;
#pragma unroll
                        for (int j = 0; j < 4; j++) {
                            int s = s0 + j;
                            int u = s / 3, d = s - 3 * u;
                            float yvd = (d == 0) ? yv0 : ((d == 1) ? yv1 : yv2);
                            v[j] = gw[u] * yvd * wt[64 + u];
                        }
                    } else {                             // m1b
                        const int s0 = t0 - 288;
#pragma unroll
                        for (int j = 0; j < 4; j++) {
                            int s = s0 + j;
                            int u = s / 3;
                            v[j] = gw[64 + s] * ys * wt[128 + u];
                        }
                    }
                    if (valid) red4(&mb[t0], v[0], v[1], v[2], v[3]);
                }
                __syncwarp();
            }
        }
        __syncthreads();
    }
}

// ---------------------------------------------------------------- node post
// 2 nodes per warp (proven).
#define PST_W0  0
#define PST_W1  24576
#define PST_L3  36864
#define PST_MID 37376
#define PST_SMEM 61952

__global__ __launch_bounds__(256) void k_nodepost(
    const float* __restrict__ attr, const float* __restrict__ l2w0,
    const float* __restrict__ l2w1, const float* __restrict__ l3,
    const int* __restrict__ nn, float* __restrict__ out, int N)
{
    extern __shared__ unsigned char sbq[];
    float* s_w0  = (float*)(sbq + PST_W0);
    float* s_w1  = (float*)(sbq + PST_W1);
    float* s_l3  = (float*)(sbq + PST_L3);
    float* s_mid = (float*)(sbq + PST_MID);   // 16 rows x 384

    for (int i = threadIdx.x; i < 6144; i += 256) s_w0[i] = l2w0[i];
    for (int i = threadIdx.x; i < 3072; i += 256) s_w1[i] = l2w1[i];
    if (threadIdx.x < 96) s_l3[threadIdx.x] = l3[threadIdx.x];

    float ms = rsqrtf((float)nn[0]);
    const float SC = 0.10206207261596575f;
    int wrp = threadIdx.x >> 5, l = threadIdx.x & 31;
    int n0 = blockIdx.x * 16 + wrp * 2;
    int n1 = n0 + 1;
    bool v0 = n0 < N, v1 = n1 < N;
    float* mr0 = &s_mid[(wrp * 2) * 384];
    float* mr1 = &s_mid[(wrp * 2 + 1) * 384];
    if (v0) {
#pragma unroll
        for (int i = 0; i < 12; i++) mr0[l + 32 * i] = g_mid[(size_t)n0 * 384 + l + 32 * i];
    }
    if (v1) {
#pragma unroll
        for (int i = 0; i < 12; i++) mr1[l + 32 * i] = g_mid[(size_t)n1 * 384 + l + 32 * i];
    }
    __syncthreads();
    if (!v0) return;

    float a0 = attr[n0];
    float a1 = v1 ? attr[n1] : 0.f;
    int w_[3], d_[3];
#pragma unroll
    for (int i = 0; i < 3; i++) { int o = l + 32 * i; w_[i] = o / 3; d_[i] = o - 3 * w_[i]; }

    ull c0 = 0ull, c1 = 0ull;
    float ang0 = 0.f, ang1 = 0.f;
#pragma unroll 8
    for (int u = 0; u < 96; u++) {
        ull w = *(const ull*)&s_w0[u * 64 + 2 * l];
        float m0 = mr0[u], m1 = mr1[u];
        ffma2(c0, fdup(m0), w);
        ffma2(c1, fdup(m1), w);
        float lw = s_l3[u];
        ang0 += m0 * lw;
        ang1 += m1 * lw;
    }
    float cv0[3] = {0,0,0}, cv1[3] = {0,0,0};
#pragma unroll 4
    for (int u = 0; u < 96; u++) {
#pragma unroll
        for (int i = 0; i < 3; i++) {
            float w = s_w1[u * 32 + w_[i]];
            cv0[i] += mr0[96 + 3 * u + d_[i]] * w;
            cv1[i] += mr1[96 + 3 * u + d_[i]] * w;
        }
    }
    {
        float sA = SC * ms * a0;
        float angle = 0.1f * ang0 * sA;
        float sa, ca; sincosf(angle, &sa, &ca);
        const float* scrow = &g_sc[(size_t)n0 * 160];
        float* orow = &out[(size_t)n0 * 160];
        float2 cc = funpack(c0);
        float2 sc2 = *(const float2*)&scrow[2 * l];
        *(float2*)&orow[2 * l] = make_float2(ca * sc2.x + sa * (cc.x * sA),
                                             ca * sc2.y + sa * (cc.y * sA));
#pragma unroll
        for (int i = 0; i < 3; i++)
            orow[64 + l + 32 * i] = ca * scrow[64 + l + 32 * i] + sa * (cv0[i] * sA);
    }
    if (v1) {
        float sA = SC * ms * a1;
        float angle = 0.1f * ang1 * sA;
        float sa, ca; sincosf(angle, &sa, &ca);
        const float* scrow = &g_sc[(size_t)n1 * 160];
        float* orow = &out[(size_t)n1 * 160];
        float2 cc = funpack(c1);
        float2 sc2 = *(const float2*)&scrow[2 * l];
        *(float2*)&orow[2 * l] = make_float2(ca * sc2.x + sa * (cc.x * sA),
                                             ca * sc2.y + sa * (cc.y * sA));
#pragma unroll
        for (int i = 0; i < 3; i++)
            orow[64 + l + 32 * i] = ca * scrow[64 + l + 32 * i] + sa * (cv1[i] * sA);
    }
}

// ---------------------------------------------------------------- launch
extern "C" void kernel_launch(void* const* d_in, const int* in_sizes, int n_in,
                              void* d_out, int out_size)
{
    const float* node_input   = (const float*)d_in[0];
    const float* node_attr    = (const float*)d_in[1];
    const float* edge_attr    = (const float*)d_in[2];
    const float* edge_scalars = (const float*)d_in[3];
    const float* sc_w0        = (const float*)d_in[4];
    const float* sc_w1        = (const float*)d_in[5];
    const float* lin1_w0      = (const float*)d_in[6];
    const float* lin1_w1      = (const float*)d_in[7];
    const float* fc_w1        = (const float*)d_in[8];
    const float* fc_w2        = (const float*)d_in[9];
    const float* lin2_w0      = (const float*)d_in[10];
    const float* lin2_w1      = (const float*)d_in[11];
    const float* lin3_w       = (const float*)d_in[12];
    const int*   edge_src     = (const int*)d_in[13];
    const int*   edge_dst     = (const int*)d_in[14];
    const int*   num_neigh    = (const int*)d_in[15];
    float* out = (float*)d_out;

    int N = in_sizes[0] / 160;
    int E = in_sizes[2] / 4;

    cudaFuncSetAttribute(k_nodepre, cudaFuncAttributeMaxDynamicSharedMemorySize, PRE_SMEM);
    k_nodepre<<<(N + 15) / 16, 256, PRE_SMEM>>>(node_input, node_attr, sc_w0, sc_w1,
                                                lin1_w0, lin1_w1, N);

    // dummy launch: shifts ncu's captured-launch slot onto k_edge
    k_dummy<<<1, 32>>>();

    cudaFuncSetAttribute(k_edge, cudaFuncAttributeMaxDynamicSharedMemorySize, K13_SMEM);
    k_edge<<<296, 256, K13_SMEM>>>(edge_attr, edge_scalars, fc_w1, fc_w2,
                                   edge_src, edge_dst, E);

    cudaFuncSetAttribute(k_nodepost, cudaFuncAttributeMaxDynamicSharedMemorySize, PST_SMEM);
    k_nodepost<<<(N + 15) / 16, 256, PST_SMEM>>>(node_attr, lin2_w0, lin2_w1, lin3_w,
                                                 num_neigh, out, N);
}

// round 16
// speedup vs baseline: 1.2061x; 1.0358x over previous
#include <cuda_runtime.h>
#include <cuda_bf16.h>
#include <cstdint>

// ---------------------------------------------------------------------------
// Convolution_29738353557732 : e3nn-style graph conv
// R16: k_edge 2-barrier pipeline (double-buffered stage); nodepost vector
//      relayout (lane=w, broadcast mids).
// ---------------------------------------------------------------------------

#define NMAX 50176
typedef unsigned long long ull;

__device__ float g_f  [NMAX * 160];
__device__ float g_sc [NMAX * 160];
__device__ float g_mid[NMAX * 384];

__device__ __forceinline__ void red4(float* p, float a, float b, float c, float d) {
    asm volatile("red.global.add.v4.f32 [%0], {%1,%2,%3,%4};"
                 :: "l"(p), "f"(a), "f"(b), "f"(c), "f"(d) : "memory");
}
__device__ __forceinline__ ull fdup(float x) {
    ull r; asm("mov.b64 %0, {%1, %1};" : "=l"(r) : "f"(x)); return r;
}
__device__ __forceinline__ void ffma2(ull& acc, ull a, ull b) {
    asm("fma.rn.f32x2 %0, %1, %2, %0;" : "+l"(acc) : "l"(a), "l"(b));
}
__device__ __forceinline__ float2 funpack(ull p) {
    float lo, hi; asm("mov.b64 {%0, %1}, %2;" : "=f"(lo), "=f"(hi) : "l"(p));
    return make_float2(lo, hi);
}

__global__ void k_dummy() {}

// ---------------------------------------------------------------- node pre
// 2 nodes per warp (proven). Also zeroes g_mid.
#define PRE_SCW0 0
#define PRE_L1W0 16384
#define PRE_SCW1 32768
#define PRE_L1W1 36864
#define PRE_X    40960
#define PRE_SMEM 51200

__global__ __launch_bounds__(256) void k_nodepre(
    const float* __restrict__ x, const float* __restrict__ attr,
    const float* __restrict__ sc_w0, const float* __restrict__ sc_w1,
    const float* __restrict__ l1w0, const float* __restrict__ l1w1, int N)
{
    extern __shared__ unsigned char sbp[];
    float* s_scw0 = (float*)(sbp + PRE_SCW0);
    float* s_l1w0 = (float*)(sbp + PRE_L1W0);
    float* s_scw1 = (float*)(sbp + PRE_SCW1);
    float* s_l1w1 = (float*)(sbp + PRE_L1W1);
    float* s_x    = (float*)(sbp + PRE_X);     // 16 rows x 160

    {   // zero g_mid (grid-stride)
        float4* m4 = reinterpret_cast<float4*>(g_mid);
        int tot = N * 96;
        int stride = gridDim.x * 256;
        for (int i = blockIdx.x * 256 + threadIdx.x; i < tot; i += stride)
            m4[i] = make_float4(0.f, 0.f, 0.f, 0.f);
    }

    for (int i = threadIdx.x; i < 4096; i += 256) { s_scw0[i] = sc_w0[i]; s_l1w0[i] = l1w0[i]; }
    for (int i = threadIdx.x; i < 1024; i += 256) { s_scw1[i] = sc_w1[i]; s_l1w1[i] = l1w1[i]; }

    int wrp = threadIdx.x >> 5, l = threadIdx.x & 31;
    int n0 = blockIdx.x * 16 + wrp * 2;
    int n1 = n0 + 1;
    bool v0 = n0 < N, v1 = n1 < N;
    float* xr0 = &s_x[(wrp * 2) * 160];
    float* xr1 = &s_x[(wrp * 2 + 1) * 160];
    if (v0) {
#pragma unroll
        for (int i = 0; i < 5; i++) xr0[l + 32 * i] = x[(size_t)n0 * 160 + l + 32 * i];
    }
    if (v1) {
#pragma unroll
        for (int i = 0; i < 5; i++) xr1[l + 32 * i] = x[(size_t)n1 * 160 + l + 32 * i];
    }
    __syncthreads();
    if (!v0) return;

    float a0 = attr[n0];
    float a1 = v1 ? attr[n1] : 0.f;
    int w_[3], d_[3];
#pragma unroll
    for (int i = 0; i < 3; i++) { int o = l + 32 * i; w_[i] = o / 3; d_[i] = o - 3 * w_[i]; }

    ull af0 = 0ull, as0 = 0ull, af1 = 0ull, as1 = 0ull;
#pragma unroll 8
    for (int u = 0; u < 64; u++) {
        ull wl = *(const ull*)&s_l1w0[u * 64 + 2 * l];
        ull ws = *(const ull*)&s_scw0[u * 64 + 2 * l];
        ull x0 = fdup(xr0[u]);
        ull x1 = fdup(xr1[u]);
        ffma2(af0, x0, wl); ffma2(as0, x0, ws);
        ffma2(af1, x1, wl); ffma2(as1, x1, ws);
    }
    float fv0[3] = {0,0,0}, sv0[3] = {0,0,0}, fv1[3] = {0,0,0}, sv1[3] = {0,0,0};
#pragma unroll 4
    for (int u = 0; u < 32; u++) {
#pragma unroll
        for (int i = 0; i < 3; i++) {
            float wl = s_l1w1[u * 32 + w_[i]];
            float ws = s_scw1[u * 32 + w_[i]];
            float xv0 = xr0[64 + 3 * u + d_[i]];
            float xv1 = xr1[64 + 3 * u + d_[i]];
            fv0[i] += xv0 * wl;  sv0[i] += xv0 * ws;
            fv1[i] += xv1 * wl;  sv1[i] += xv1 * ws;
        }
    }
    {
        float* fo = &g_f[(size_t)n0 * 160];
        float* so = &g_sc[(size_t)n0 * 160];
        float S1 = 0.125f * a0, S2 = 0.17677669529663687f * a0;
        float2 ff = funpack(af0), ss = funpack(as0);
        *(float2*)&fo[2 * l] = make_float2(ff.x * S1, ff.y * S1);
        *(float2*)&so[2 * l] = make_float2(ss.x * S1, ss.y * S1);
#pragma unroll
        for (int i = 0; i < 3; i++) {
            fo[64 + l + 32 * i] = fv0[i] * S2;
            so[64 + l + 32 * i] = sv0[i] * S2;
        }
    }
    if (v1) {
        float* fo = &g_f[(size_t)n1 * 160];
        float* so = &g_sc[(size_t)n1 * 160];
        float S1 = 0.125f * a1, S2 = 0.17677669529663687f * a1;
        float2 ff = funpack(af1), ss = funpack(as1);
        *(float2*)&fo[2 * l] = make_float2(ff.x * S1, ff.y * S1);
        *(float2*)&so[2 * l] = make_float2(ss.x * S1, ss.y * S1);
#pragma unroll
        for (int i = 0; i < 3; i++) {
            fo[64 + l + 32 * i] = fv1[i] * S2;
            so[64 + l + 32 * i] = sv1[i] * S2;
        }
    }
}

// ---------------------------------------------------------------- edge kernel
// TILE_E=48, 256 threads, 2 CTAs/SM. 2 barriers/tile:
//   phase1(buf) ; sync ; phase2 ; syncwarp ; phase3(buf) ; stage(t+1, buf^1) ; sync
#define TILE_E 48
#define HS 50

#define O_H    0                    // 64*50*4      = 12800
#define O_W2   12800                // 49152
#define O_WT   61952                // 48*192*4     = 36864
#define O_W1T  98816                // 2048
#define O_ES   100864               // 2 x 1536
#define O_EA   103936               // 2 x 768
#define O_SRC  105472               // 2 x 192
#define O_DST  105856               // 2 x 192
#define O_G    106240               // 8*160*4      = 5120
#define K16_SMEM 111360

__global__ __launch_bounds__(256, 2) void k_edge(
    const float* __restrict__ edge_attr, const float* __restrict__ edge_scalars,
    const float* __restrict__ fc_w1, const float* __restrict__ fc_w2,
    const int* __restrict__ edge_src, const int* __restrict__ edge_dst, int E)
{
    extern __shared__ unsigned char sb[];
    float*  s_h   = (float*)(sb + O_H);
    float*  s_w2  = (float*)(sb + O_W2);
    float*  s_wt  = (float*)(sb + O_WT);
    float*  s_w1t = (float*)(sb + O_W1T);
    float*  s_g   = (float*)(sb + O_G);

    const int tid = threadIdx.x;
    const int wrp = tid >> 5, l = tid & 31;

    for (int i = tid; i < 512; i += 256) {
        int c = i >> 6, j = i & 63;            // w1t[j*8+c] = fc_w1[c*64+j]
        s_w1t[j * 8 + c] = fc_w1[i];
    }
    for (int i = tid; i < 12288; i += 256) s_w2[i] = fc_w2[i] * 0.125f;

    const int ntiles = (E + TILE_E - 1) / TILE_E;
    const int eb = wrp * 6;                    // phase-2/3: 6 edges per warp

    // phase-1 fixed assignment: j = tid & 63, e-group = tid >> 6 (0..3)
    const int p1j = tid & 63;
    const int p1eg = tid >> 6;
    float* const p1out = &s_h[p1j * HS];

    // stage helper (lambda-free, inlined twice)
#define STAGE(TSTAGE, B) do {                                                  \
        float* _es  = (float*)(sb + O_ES  + (B) * 1536);                       \
        float4* _ea = (float4*)(sb + O_EA + (B) * 768);                        \
        int* _src   = (int*)(sb + O_SRC + (B) * 192);                          \
        int* _dst   = (int*)(sb + O_DST + (B) * 192);                          \
        int _e0 = (TSTAGE) * TILE_E;                                           \
        if (tid < 96) {                                                        \
            int e = tid >> 1, h = tid & 1, ge = _e0 + e;                       \
            float4 v = make_float4(0.f, 0.f, 0.f, 0.f);                        \
            if (ge < E) v = *(const float4*)&edge_scalars[(size_t)ge * 8 + 4 * h]; \
            *(float4*)&_es[e * 8 + 4 * h] = v;                                 \
        } else if (tid < 144) {                                                \
            int e = tid - 96, ge = _e0 + e;                                    \
            _ea[e] = (ge < E) ? *(const float4*)&edge_attr[(size_t)ge * 4]     \
                              : make_float4(0.f, 0.f, 0.f, 0.f);               \
        } else if (tid < 192) {                                                \
            int e = tid - 144, ge = _e0 + e;                                   \
            _src[e] = (ge < E) ? edge_src[ge] : 0;                             \
            _dst[e] = (ge < E) ? edge_dst[ge] : 0;                             \
        }                                                                      \
    } while (0)

    // prologue: stage first tile into buf 0 (weights loaded above too)
    STAGE(blockIdx.x, 0);
    __syncthreads();

    const float4 wa = *(const float4*)&s_w1t[p1j * 8];
    const float4 wb = *(const float4*)&s_w1t[p1j * 8 + 4];

    int buf = 0;
    for (int tile = blockIdx.x; tile < ntiles; tile += gridDim.x) {
        const int e0 = tile * TILE_E;
        float*  s_es  = (float*)(sb + O_ES  + buf * 1536);
        float4* s_ea4 = (float4*)(sb + O_EA + buf * 768);
        int*    s_src = (int*)(sb + O_SRC + buf * 192);
        int*    s_dst = (int*)(sb + O_DST + buf * 192);

        // ---- phase 1: h = silu(es @ fc_w1 / sqrt(8)); j fixed, e = eg + 4k
#pragma unroll
        for (int k = 0; k < 12; k++) {
            int e = p1eg + 4 * k;
            float4 A = *(const float4*)&s_es[e * 8];
            float4 B = *(const float4*)&s_es[e * 8 + 4];
            float acc = A.x * wa.x + A.y * wa.y + A.z * wa.z + A.w * wa.w
                      + B.x * wb.x + B.y * wb.y + B.z * wb.z + B.w * wb.w;
            acc *= 0.3535533905932738f;
            p1out[e] = __fdividef(acc, 1.f + __expf(-acc));
        }
        __syncthreads();

        // ---- phase 2: wt = h @ (0.125*w2); warp = 6 edges x 192 outs
        {
            ull acc[6][3];
#pragma unroll
            for (int a = 0; a < 6; a++)
#pragma unroll
                for (int b = 0; b < 3; b++) acc[a][b] = 0ull;

#pragma unroll 4
            for (int j = 0; j < 64; j++) {
                const float2* hp = (const float2*)&s_h[j * HS + eb];
                float2 h01 = hp[0], h23 = hp[1], h45 = hp[2];
                ull hd[6];
                hd[0] = fdup(h01.x); hd[1] = fdup(h01.y);
                hd[2] = fdup(h23.x); hd[3] = fdup(h23.y);
                hd[4] = fdup(h45.x); hd[5] = fdup(h45.y);
                const ull* wp = (const ull*)&s_w2[j * 192 + 2 * l];
                ull w0 = wp[0], w1v = wp[32], w2v = wp[64];
#pragma unroll
                for (int e = 0; e < 6; e++) {
                    ffma2(acc[e][0], hd[e], w0);
                    ffma2(acc[e][1], hd[e], w1v);
                    ffma2(acc[e][2], hd[e], w2v);
                }
            }
#pragma unroll
            for (int e = 0; e < 6; e++) {
                ull* outp = (ull*)&s_wt[(eb + e) * 192 + 2 * l];
                outp[0]  = acc[e][0];
                outp[32] = acc[e][1];
                outp[64] = acc[e][2];
            }
        }
        __syncwarp();   // s_wt warp-local visibility (phase3 reads other lanes' stores)

        // ---- phase 3: prefetched gather + features + red.v4 scatter
        {
            float* gw = &s_g[wrp * 160];
            float4* gw4 = (float4*)gw;

            float4 pa, pb;
            {
                const float4* fr = (const float4*)&g_f[(size_t)s_src[eb] * 160];
                pa = fr[l];
                pb = (l < 8) ? fr[32 + l] : make_float4(0.f, 0.f, 0.f, 0.f);
            }

#pragma unroll
            for (int ee = 0; ee < 6; ee++) {
                const int e = eb + ee;
                const bool valid = (e0 + e) < E;

                gw4[l] = pa;
                if (l < 8) gw4[32 + l] = pb;
                if (ee < 5) {
                    const float4* fr = (const float4*)&g_f[(size_t)s_src[e + 1] * 160];
                    pa = fr[l];
                    if (l < 8) pb = fr[32 + l];
                }
                __syncwarp();

                float4 ea = s_ea4[e];
                const float ys = ea.x, yv0 = ea.y, yv1 = ea.z, yv2 = ea.w;
                const float* wt = &s_wt[e * 192];
                float* mb = &g_mid[(size_t)s_dst[e] * 384];

#pragma unroll
                for (int i = 0; i < 3; i++) {
                    const int t0 = i * 128 + 4 * l;
                    float v[4];
                    if (t0 < 64) {                       // m0a
#pragma unroll
                        for (int j = 0; j < 4; j++) v[j] = gw[t0 + j] * ys * wt[t0 + j];
                    } else if (t0 < 96) {                // m0b
                        const int c0 = t0 - 64;
#pragma unroll
                        for (int j = 0; j < 4; j++) {
                            int c = c0 + j;
                            float dot = gw[64 + 3 * c] * yv0 + gw[65 + 3 * c] * yv1
                                      + gw[66 + 3 * c] * yv2;
                            v[j] = dot * 0.5773502691896258f * wt[160 + c];
                        }
                    } else if (t0 < 288) {               // m1a
                        const int s0 = t0 - 96;
#pragma unroll
                        for (int j = 0; j < 4; j++) {
                            int s = s0 + j;
                            int u = s / 3, d = s - 3 * u;
                            float yvd = (d == 0) ? yv0 : ((d == 1) ? yv1 : yv2);
                            v[j] = gw[u] * yvd * wt[64 + u];
                        }
                    } else {                             // m1b
                        const int s0 = t0 - 288;
#pragma unroll
                        for (int j = 0; j < 4; j++) {
                            int s = s0 + j;
                            int u = s / 3;
                            v[j] = gw[64 + s] * ys * wt[128 + u];
                        }
                    }
                    if (valid) red4(&mb[t0], v[0], v[1], v[2], v[3]);
                }
                __syncwarp();
            }
        }

        // ---- stage next tile into the other buffer
        STAGE(tile + gridDim.x, buf ^ 1);
        __syncthreads();
        buf ^= 1;
    }
#undef STAGE
}

// ---------------------------------------------------------------- node post
// 2 nodes per warp; vector part: lane l owns w=l (stride-1 w1 reads, bcast mids).
#define PST_W0  0
#define PST_W1  24576
#define PST_L3  36864
#define PST_MID 37376
#define PST_SMEM 61952

__global__ __launch_bounds__(256) void k_nodepost(
    const float* __restrict__ attr, const float* __restrict__ l2w0,
    const float* __restrict__ l2w1, const float* __restrict__ l3,
    const int* __restrict__ nn, float* __restrict__ out, int N)
{
    extern __shared__ unsigned char sbq[];
    float* s_w0  = (float*)(sbq + PST_W0);
    float* s_w1  = (float*)(sbq + PST_W1);
    float* s_l3  = (float*)(sbq + PST_L3);
    float* s_mid = (float*)(sbq + PST_MID);   // 16 rows x 384

    for (int i = threadIdx.x; i < 6144; i += 256) s_w0[i] = l2w0[i];
    for (int i = threadIdx.x; i < 3072; i += 256) s_w1[i] = l2w1[i];
    if (threadIdx.x < 96) s_l3[threadIdx.x] = l3[threadIdx.x];

    float ms = rsqrtf((float)nn[0]);
    const float SC = 0.10206207261596575f;
    int wrp = threadIdx.x >> 5, l = threadIdx.x & 31;
    int n0 = blockIdx.x * 16 + wrp * 2;
    int n1 = n0 + 1;
    bool v0 = n0 < N, v1 = n1 < N;
    float* mr0 = &s_mid[(wrp * 2) * 384];
    float* mr1 = &s_mid[(wrp * 2 + 1) * 384];
    if (v0) {
#pragma unroll
        for (int i = 0; i < 12; i++) mr0[l + 32 * i] = g_mid[(size_t)n0 * 384 + l + 32 * i];
    }
    if (v1) {
#pragma unroll
        for (int i = 0; i < 12; i++) mr1[l + 32 * i] = g_mid[(size_t)n1 * 384 + l + 32 * i];
    }
    __syncthreads();
    if (!v0) return;

    float a0 = attr[n0];
    float a1 = v1 ? attr[n1] : 0.f;

    ull c0 = 0ull, c1 = 0ull;
    float ang0 = 0.f, ang1 = 0.f;
#pragma unroll 8
    for (int u = 0; u < 96; u++) {
        ull w = *(const ull*)&s_w0[u * 64 + 2 * l];
        float m0 = mr0[u], m1 = mr1[u];
        ffma2(c0, fdup(m0), w);
        ffma2(c1, fdup(m1), w);
        float lw = s_l3[u];
        ang0 += m0 * lw;
        ang1 += m1 * lw;
    }
    // vector part: lane l owns output w=l, all 3 d components
    float cv0[3] = {0,0,0}, cv1[3] = {0,0,0};
#pragma unroll 4
    for (int u = 0; u < 96; u++) {
        float w = s_w1[u * 32 + l];
#pragma unroll
        for (int d = 0; d < 3; d++) {
            cv0[d] += mr0[96 + 3 * u + d] * w;
            cv1[d] += mr1[96 + 3 * u + d] * w;
        }
    }
    {
        float sA = SC * ms * a0;
        float angle = 0.1f * ang0 * sA;
        float sa, ca; sincosf(angle, &sa, &ca);
        const float* scrow = &g_sc[(size_t)n0 * 160];
        float* orow = &out[(size_t)n0 * 160];
        float2 cc = funpack(c0);
        float2 sc2 = *(const float2*)&scrow[2 * l];
        *(float2*)&orow[2 * l] = make_float2(ca * sc2.x + sa * (cc.x * sA),
                                             ca * sc2.y + sa * (cc.y * sA));
#pragma unroll
        for (int d = 0; d < 3; d++)
            orow[64 + 3 * l + d] = ca * scrow[64 + 3 * l + d] + sa * (cv0[d] * sA);
    }
    if (v1) {
        float sA = SC * ms * a1;
        float angle = 0.1f * ang1 * sA;
        float sa, ca; sincosf(angle, &sa, &ca);
        const float* scrow = &g_sc[(size_t)n1 * 160];
        float* orow = &out[(size_t)n1 * 160];
        float2 cc = funpack(c1);
        float2 sc2 = *(const float2*)&scrow[2 * l];
        *(float2*)&orow[2 * l] = make_float2(ca * sc2.x + sa * (cc.x * sA),
                                             ca * sc2.y + sa * (cc.y * sA));
#pragma unroll
        for (int d = 0; d < 3; d++)
            orow[64 + 3 * l + d] = ca * scrow[64 + 3 * l + d] + sa * (cv1[d] * sA);
    }
}

// ---------------------------------------------------------------- launch
extern "C" void kernel_launch(void* const* d_in, const int* in_sizes, int n_in,
                              void* d_out, int out_size)
{
    const float* node_input   = (const float*)d_in[0];
    const float* node_attr    = (const float*)d_in[1];
    const float* edge_attr    = (const float*)d_in[2];
    const float* edge_scalars = (const float*)d_in[3];
    const float* sc_w0        = (const float*)d_in[4];
    const float* sc_w1        = (const float*)d_in[5];
    const float* lin1_w0      = (const float*)d_in[6];
    const float* lin1_w1      = (const float*)d_in[7];
    const float* fc_w1        = (const float*)d_in[8];
    const float* fc_w2        = (const float*)d_in[9];
    const float* lin2_w0      = (const float*)d_in[10];
    const float* lin2_w1      = (const float*)d_in[11];
    const float* lin3_w       = (const float*)d_in[12];
    const int*   edge_src     = (const int*)d_in[13];
    const int*   edge_dst     = (const int*)d_in[14];
    const int*   num_neigh    = (const int*)d_in[15];
    float* out = (float*)d_out;

    int N = in_sizes[0] / 160;
    int E = in_sizes[2] / 4;

    cudaFuncSetAttribute(k_nodepre, cudaFuncAttributeMaxDynamicSharedMemorySize, PRE_SMEM);
    k_nodepre<<<(N + 15) / 16, 256, PRE_SMEM>>>(node_input, node_attr, sc_w0, sc_w1,
                                                lin1_w0, lin1_w1, N);

    // dummy launch keeps the launch pattern of R13/R15 (profiling slot)
    k_dummy<<<1, 32>>>();

    cudaFuncSetAttribute(k_edge, cudaFuncAttributeMaxDynamicSharedMemorySize, K16_SMEM);
    k_edge<<<296, 256, K16_SMEM>>>(edge_attr, edge_scalars, fc_w1, fc_w2,
                                   edge_src, edge_dst, E);

    cudaFuncSetAttribute(k_nodepost, cudaFuncAttributeMaxDynamicSharedMemorySize, PST_SMEM);
    k_nodepost<<<(N + 15) / 16, 256, PST_SMEM>>>(node_attr, lin2_w0, lin2_w1, lin3_w,
                                                 num_neigh, out, N);
}